// round 1
// baseline (speedup 1.0000x reference)
#include <cuda_runtime.h>
#include <math.h>

#define B_ 2
#define S_ 2048
#define HID_ 2048
#define HEADS_ 16
#define GROUPS_ 4
#define KVC_ 128
// q/kv/ctx scratch (device globals: no allocs allowed)
__device__ float g_q[(size_t)B_ * S_ * HEADS_ * KVC_];        // [b,s,h,d]
__device__ float g_kv[(size_t)B_ * S_ * 2 * GROUPS_ * KVC_];  // [b,s,sel,g,d]
__device__ float g_ctx[(size_t)B_ * S_ * HEADS_ * KVC_];      // [b,s,h,d]
__device__ float g_cos[S_ * 64];
__device__ float g_sin[S_ * 64];

// ---------------------------------------------------------------------------
// Classic 128x128x8 SGEMM, 256 threads, 8x8 microtile. A[M,K], B[K,N] row-major.
// All shapes here are multiples of 128 (M=4096, N in {2048,1024}, K=2048).
// ---------------------------------------------------------------------------
__global__ __launch_bounds__(256) void sgemm128(
    int M, int N, int K,
    const float* __restrict__ A, const float* __restrict__ B,
    float* __restrict__ C) {
  __shared__ float As[8][128];
  __shared__ float Bs[8][128];
  const int tid = threadIdx.x;
  const int tcol = tid & 15;
  const int trow = tid >> 4;
  const float* Ab = A + (size_t)blockIdx.y * 128 * K;
  const float* Bb = B + blockIdx.x * 128;
  float* Cb = C + (size_t)blockIdx.y * 128 * N + blockIdx.x * 128;
  const int aRow = tid >> 1;
  const int aCol = (tid & 1) * 4;
  const int bRow = tid >> 5;
  const int bCol = (tid & 31) * 4;

  float acc[8][8];
#pragma unroll
  for (int i = 0; i < 8; i++)
#pragma unroll
    for (int j = 0; j < 8; j++) acc[i][j] = 0.f;

  for (int k0 = 0; k0 < K; k0 += 8) {
    float4 av = *(const float4*)(Ab + (size_t)aRow * K + k0 + aCol);
    As[aCol + 0][aRow] = av.x;
    As[aCol + 1][aRow] = av.y;
    As[aCol + 2][aRow] = av.z;
    As[aCol + 3][aRow] = av.w;
    *(float4*)(&Bs[bRow][bCol]) =
        *(const float4*)(Bb + (size_t)(k0 + bRow) * N + bCol);
    __syncthreads();
#pragma unroll
    for (int kk = 0; kk < 8; kk++) {
      float ar[8], br[8];
      *(float4*)(ar) = *(const float4*)(&As[kk][trow * 8]);
      *(float4*)(ar + 4) = *(const float4*)(&As[kk][trow * 8 + 4]);
      *(float4*)(br) = *(const float4*)(&Bs[kk][tcol * 8]);
      *(float4*)(br + 4) = *(const float4*)(&Bs[kk][tcol * 8 + 4]);
#pragma unroll
      for (int i = 0; i < 8; i++)
#pragma unroll
        for (int j = 0; j < 8; j++) acc[i][j] += ar[i] * br[j];
    }
    __syncthreads();
  }
#pragma unroll
  for (int i = 0; i < 8; i++) {
    float* crow = Cb + (size_t)(trow * 8 + i) * N + tcol * 8;
    *(float4*)(crow) = make_float4(acc[i][0], acc[i][1], acc[i][2], acc[i][3]);
    *(float4*)(crow + 4) = make_float4(acc[i][4], acc[i][5], acc[i][6], acc[i][7]);
  }
}

// ---------------------------------------------------------------------------
// RoPE tables (double precision host-of-truth, cast to fp32)
// ---------------------------------------------------------------------------
__global__ void rope_tables_k() {
  int i = blockIdx.x * blockDim.x + threadIdx.x;  // S_*64
  if (i >= S_ * 64) return;
  int s = i >> 6, f = i & 63;
  double inv = exp(-((double)(2 * f) / 128.0) * log(10000.0));
  double ang = (double)s * inv;
  g_cos[i] = (float)cos(ang);
  g_sin[i] = (float)sin(ang);
}

// Apply RoPE in place to q (16 heads) and k (kv sel=0, 4 heads)
__global__ void rope_apply_k() {
  int idx = blockIdx.x * blockDim.x + threadIdx.x;  // B*S*20*64
  if (idx >= B_ * S_ * (HEADS_ + GROUPS_) * 64) return;
  int f = idx & 63;
  int t = idx >> 6;
  int hh = t % (HEADS_ + GROUPS_);
  t /= (HEADS_ + GROUPS_);
  int s = t % S_;
  int b = t / S_;
  float c = g_cos[s * 64 + f];
  float sn = g_sin[s * 64 + f];
  float* base;
  if (hh < HEADS_) {
    base = g_q + ((size_t)((size_t)b * S_ + s) * HEADS_ + hh) * KVC_;
  } else {
    base = g_kv + (size_t)((size_t)b * S_ + s) * (2 * GROUPS_ * KVC_) +
           (hh - HEADS_) * KVC_;  // sel=0 (k)
  }
  float x1 = base[f];
  float x2 = base[f + 64];
  base[f] = x1 * c - x2 * sn;
  base[f + 64] = x2 * c + x1 * sn;
}

// ---------------------------------------------------------------------------
// Causal flash attention, fp32. BLOCK_M=64, BLOCK_N=64, D=128.
// 256 threads = 16x16 grid, 4x4 microtile for S, 4x8 for O (interleaved cols).
// ---------------------------------------------------------------------------
#define QT_ST 68   // transposed Q/K tile row stride (floats)
#define VS_ST 132  // V tile row stride
#define PS_ST 68   // P tile row stride
#define ATTN_SMEM ((128 * QT_ST * 2 + 64 * VS_ST + 64 * PS_ST) * 4)

__global__ __launch_bounds__(256) void attn64() {
  extern __shared__ float sm[];
  float* Qt = sm;                  // [128][QT_ST] q^T * scale
  float* Kt = Qt + 128 * QT_ST;    // [128][QT_ST] k^T
  float* Vs = Kt + 128 * QT_ST;    // [64][VS_ST]
  float* Ps = Vs + 64 * VS_ST;     // [64][PS_ST]
  const int qtile = blockIdx.x;    // 0..31
  const int b = blockIdx.y >> 4;
  const int h = blockIdx.y & 15;
  const int g = h >> 2;
  const int tid = threadIdx.x;
  const int tx = tid & 15, ty = tid >> 4;
  const int r0 = ty * 4, c0 = tx * 4;
  const float scale = 0.088388347648318447f;  // 128^-0.5

  // load Q tile (64 x 128), transposed + pre-scaled
  const float* Qg = g_q + ((size_t)((size_t)b * S_ + qtile * 64) * HEADS_ + h) * KVC_;
  for (int i = tid; i < 64 * 32; i += 256) {
    int r = i >> 5, d = (i & 31) * 4;
    float4 v = *(const float4*)(Qg + (size_t)r * (HEADS_ * KVC_) + d);
    Qt[(d + 0) * QT_ST + r] = v.x * scale;
    Qt[(d + 1) * QT_ST + r] = v.y * scale;
    Qt[(d + 2) * QT_ST + r] = v.z * scale;
    Qt[(d + 3) * QT_ST + r] = v.w * scale;
  }

  float m[4], l[4], O[4][8];
#pragma unroll
  for (int i = 0; i < 4; i++) {
    m[i] = -1e30f;
    l[i] = 0.f;
#pragma unroll
    for (int j = 0; j < 8; j++) O[i][j] = 0.f;
  }

  for (int jt = 0; jt <= qtile; jt++) {
    const float* Kg = g_kv + (size_t)((size_t)b * S_ + jt * 64) * (2 * GROUPS_ * KVC_) + g * KVC_;
    const float* Vg = Kg + GROUPS_ * KVC_;  // sel=1 offset
    __syncthreads();  // previous iter done reading Kt/Vs/Ps
    for (int i = tid; i < 64 * 32; i += 256) {
      int r = i >> 5, d = (i & 31) * 4;
      float4 kv4 = *(const float4*)(Kg + (size_t)r * (2 * GROUPS_ * KVC_) + d);
      Kt[(d + 0) * QT_ST + r] = kv4.x;
      Kt[(d + 1) * QT_ST + r] = kv4.y;
      Kt[(d + 2) * QT_ST + r] = kv4.z;
      Kt[(d + 3) * QT_ST + r] = kv4.w;
      *(float4*)(Vs + r * VS_ST + d) =
          *(const float4*)(Vg + (size_t)r * (2 * GROUPS_ * KVC_) + d);
    }
    __syncthreads();

    // S[4][4] = (Qt^T)[r0..][*] . (Kt^T)[c0..][*]
    float s[4][4];
#pragma unroll
    for (int i = 0; i < 4; i++)
#pragma unroll
      for (int j = 0; j < 4; j++) s[i][j] = 0.f;
#pragma unroll 4
    for (int kk = 0; kk < 128; kk++) {
      float4 a = *(const float4*)(Qt + kk * QT_ST + r0);
      float4 bb = *(const float4*)(Kt + kk * QT_ST + c0);
      float a4[4] = {a.x, a.y, a.z, a.w};
      float b4[4] = {bb.x, bb.y, bb.z, bb.w};
#pragma unroll
      for (int i = 0; i < 4; i++)
#pragma unroll
        for (int j = 0; j < 4; j++) s[i][j] += a4[i] * b4[j];
    }
    if (jt == qtile) {  // diagonal tile: causal mask
#pragma unroll
      for (int i = 0; i < 4; i++)
#pragma unroll
        for (int j = 0; j < 4; j++)
          if (c0 + j > r0 + i) s[i][j] = -1e30f;
    }

    // online softmax (row groups of 16 lanes share a set of 4 rows)
    float rm[4];
#pragma unroll
    for (int i = 0; i < 4; i++)
      rm[i] = fmaxf(fmaxf(s[i][0], s[i][1]), fmaxf(s[i][2], s[i][3]));
#pragma unroll
    for (int off = 1; off < 16; off <<= 1)
#pragma unroll
      for (int i = 0; i < 4; i++)
        rm[i] = fmaxf(rm[i], __shfl_xor_sync(0xffffffffu, rm[i], off));

    float rs[4];
#pragma unroll
    for (int i = 0; i < 4; i++) {
      float mn = fmaxf(m[i], rm[i]);
      float al = expf(m[i] - mn);
      float p0 = expf(s[i][0] - mn);
      float p1 = expf(s[i][1] - mn);
      float p2 = expf(s[i][2] - mn);
      float p3 = expf(s[i][3] - mn);
      Ps[(r0 + i) * PS_ST + c0 + 0] = p0;
      Ps[(r0 + i) * PS_ST + c0 + 1] = p1;
      Ps[(r0 + i) * PS_ST + c0 + 2] = p2;
      Ps[(r0 + i) * PS_ST + c0 + 3] = p3;
      rs[i] = p0 + p1 + p2 + p3;
      l[i] = l[i] * al;
      m[i] = mn;
#pragma unroll
      for (int j = 0; j < 8; j++) O[i][j] *= al;
    }
#pragma unroll
    for (int off = 1; off < 16; off <<= 1)
#pragma unroll
      for (int i = 0; i < 4; i++)
        rs[i] += __shfl_xor_sync(0xffffffffu, rs[i], off);
#pragma unroll
    for (int i = 0; i < 4; i++) l[i] += rs[i];
    __syncthreads();  // Ps complete

    // O[r0..r0+3][j*16+tx] += P[r][c] * V[c][j*16+tx]
#pragma unroll 2
    for (int c = 0; c < 64; c++) {
      float pv[4];
#pragma unroll
      for (int i = 0; i < 4; i++) pv[i] = Ps[(r0 + i) * PS_ST + c];
#pragma unroll
      for (int j = 0; j < 8; j++) {
        float vv = Vs[c * VS_ST + j * 16 + tx];
#pragma unroll
        for (int i = 0; i < 4; i++) O[i][j] += pv[i] * vv;
      }
    }
  }

  // epilogue: normalize, write ctx [b,s,h,d]
#pragma unroll
  for (int i = 0; i < 4; i++) {
    float inv = 1.f / l[i];
    size_t row = (size_t)b * S_ + qtile * 64 + r0 + i;
    float* crow = g_ctx + (row * HEADS_ + h) * KVC_;
#pragma unroll
    for (int j = 0; j < 8; j++) crow[j * 16 + tx] = O[i][j] * inv;
  }
}

// ---------------------------------------------------------------------------
extern "C" void kernel_launch(void* const* d_in, const int* in_sizes, int n_in,
                              void* d_out, int out_size) {
  (void)in_sizes; (void)n_in; (void)out_size;
  const float* x = (const float*)d_in[0];
  const float* w_q = (const float*)d_in[1];
  const float* w_kv = (const float*)d_in[2];
  const float* w_dense = (const float*)d_in[3];
  float* out = (float*)d_out;

  float *qb, *kvb, *ctxb;
  cudaGetSymbolAddress((void**)&qb, g_q);
  cudaGetSymbolAddress((void**)&kvb, g_kv);
  cudaGetSymbolAddress((void**)&ctxb, g_ctx);

  cudaFuncSetAttribute(attn64, cudaFuncAttributeMaxDynamicSharedMemorySize,
                       ATTN_SMEM);

  const int M = B_ * S_;  // 4096
  // 1) QKV projections
  sgemm128<<<dim3((HEADS_ * KVC_) / 128, M / 128), 256>>>(
      M, HEADS_ * KVC_, HID_, x, w_q, qb);
  sgemm128<<<dim3((2 * GROUPS_ * KVC_) / 128, M / 128), 256>>>(
      M, 2 * GROUPS_ * KVC_, HID_, x, w_kv, kvb);
  // 2) RoPE
  rope_tables_k<<<(S_ * 64 + 255) / 256, 256>>>();
  rope_apply_k<<<(B_ * S_ * (HEADS_ + GROUPS_) * 64 + 255) / 256, 256>>>();
  // 3) causal GQA flash attention
  attn64<<<dim3(S_ / 64, B_ * HEADS_), 256, ATTN_SMEM>>>();
  // 4) dense projection -> out
  sgemm128<<<dim3(HID_ / 128, M / 128), 256>>>(M, HID_, HEADS_ * KVC_, ctxb,
                                               w_dense, out);
}

// round 2
// speedup vs baseline: 1.5818x; 1.5818x over previous
#include <cuda_runtime.h>
#include <math.h>
#include <stdint.h>

#define B_ 2
#define S_ 2048
#define HID_ 2048
#define HEADS_ 16
#define GROUPS_ 4
#define KVC_ 128
// scratch (device globals: no allocs allowed)
__device__ float g_q[(size_t)B_ * S_ * HEADS_ * KVC_];        // [b,s,h,d]
__device__ float g_kv[(size_t)B_ * S_ * 2 * GROUPS_ * KVC_];  // [b,s,sel,g,d]
__device__ float g_ctx[(size_t)B_ * S_ * HEADS_ * KVC_];      // [b,s,h,d]
__device__ float g_cos[S_ * 64];
__device__ float g_sin[S_ * 64];

// ---------------------------------------------------------------------------
// tf32 helpers
// ---------------------------------------------------------------------------
__device__ __forceinline__ uint32_t f2tf32(float x) {
  uint32_t r;
  asm("cvt.rna.tf32.f32 %0, %1;" : "=r"(r) : "f"(x));
  return r;
}

__device__ __forceinline__ void mma_tf32(float c[4], const uint32_t a[4],
                                         const uint32_t b[2]) {
  asm volatile(
      "mma.sync.aligned.m16n8k8.row.col.f32.tf32.tf32.f32 "
      "{%0,%1,%2,%3}, {%4,%5,%6,%7}, {%8,%9}, {%0,%1,%2,%3};\n"
      : "+f"(c[0]), "+f"(c[1]), "+f"(c[2]), "+f"(c[3])
      : "r"(a[0]), "r"(a[1]), "r"(a[2]), "r"(a[3]), "r"(b[0]), "r"(b[1]));
}

// ---------------------------------------------------------------------------
// tf32 tensor-core GEMM: C[M,N] = A[M,K] @ B[K,N], all row-major.
// Block 128x128, K-chunk 32, 256 threads = 8 warps in 4x2 grid,
// warp tile 32x64 (2 m16-tiles x 8 n8-tiles). Conflict-free smem.
// ---------------------------------------------------------------------------
__global__ __launch_bounds__(256) void tf32gemm(
    int M, int N, int K,
    const float* __restrict__ A, const float* __restrict__ B,
    float* __restrict__ C) {
  __shared__ uint32_t As[128][36];  // [row][k] pad->36 (16B-aligned rows)
  __shared__ uint32_t Bs[32][132];  // [k][col] pad->132
  const int tid = threadIdx.x;
  const int lane = tid & 31;
  const int wid = tid >> 5;
  const int gid = lane >> 2;  // 0..7
  const int tig = lane & 3;   // 0..3
  const int wr = wid >> 1;    // warp row 0..3
  const int wc = wid & 1;     // warp col 0..1
  const size_t rb = (size_t)blockIdx.y * 128;
  const int cb = blockIdx.x * 128;

  float acc[2][8][4];
#pragma unroll
  for (int mt = 0; mt < 2; mt++)
#pragma unroll
    for (int nt = 0; nt < 8; nt++)
#pragma unroll
      for (int i = 0; i < 4; i++) acc[mt][nt][i] = 0.f;

  const int arow0 = wr * 32 + gid;  // fragment A row base (mt adds 16)
  const int bcol0 = wc * 64 + gid;  // fragment B col base (nt adds 8)

  for (int k0 = 0; k0 < K; k0 += 32) {
    // ---- load A chunk 128x32 (4 float4 per thread, coalesced) ----
#pragma unroll
    for (int it = 0; it < 4; it++) {
      int idx = it * 256 + tid;
      int r = idx >> 3;            // 0..127
      int c4 = (idx & 7) * 4;      // 0..28
      float4 v = *(const float4*)(A + (rb + r) * K + k0 + c4);
      uint4 u = make_uint4(f2tf32(v.x), f2tf32(v.y), f2tf32(v.z), f2tf32(v.w));
      *(uint4*)&As[r][c4] = u;
    }
    // ---- load B chunk 32x128 (4 float4 per thread, coalesced) ----
#pragma unroll
    for (int it = 0; it < 4; it++) {
      int idx = it * 256 + tid;
      int r = idx >> 5;             // 0..31
      int c4 = (idx & 31) * 4;      // 0..124
      float4 v = *(const float4*)(B + (size_t)(k0 + r) * N + cb + c4);
      uint4 u = make_uint4(f2tf32(v.x), f2tf32(v.y), f2tf32(v.z), f2tf32(v.w));
      *(uint4*)&Bs[r][c4] = u;
    }
    __syncthreads();

#pragma unroll
    for (int kk = 0; kk < 32; kk += 8) {
      uint32_t af[2][4], bf[8][2];
#pragma unroll
      for (int mt = 0; mt < 2; mt++) {
        int r = arow0 + mt * 16;
        af[mt][0] = As[r][kk + tig];
        af[mt][1] = As[r + 8][kk + tig];
        af[mt][2] = As[r][kk + tig + 4];
        af[mt][3] = As[r + 8][kk + tig + 4];
      }
#pragma unroll
      for (int nt = 0; nt < 8; nt++) {
        int c = bcol0 + nt * 8;
        bf[nt][0] = Bs[kk + tig][c];
        bf[nt][1] = Bs[kk + tig + 4][c];
      }
#pragma unroll
      for (int mt = 0; mt < 2; mt++)
#pragma unroll
        for (int nt = 0; nt < 8; nt++) mma_tf32(acc[mt][nt], af[mt], bf[nt]);
    }
    __syncthreads();
  }

  // ---- epilogue: c0,c1 -> (row gid, cols 2tig,2tig+1); c2,c3 -> row gid+8 ----
#pragma unroll
  for (int mt = 0; mt < 2; mt++) {
#pragma unroll
    for (int nt = 0; nt < 8; nt++) {
      size_t r0 = rb + wr * 32 + mt * 16 + gid;
      int c = cb + wc * 64 + nt * 8 + tig * 2;
      float2 lo = make_float2(acc[mt][nt][0], acc[mt][nt][1]);
      float2 hi = make_float2(acc[mt][nt][2], acc[mt][nt][3]);
      *(float2*)&C[r0 * N + c] = lo;
      *(float2*)&C[(r0 + 8) * N + c] = hi;
    }
  }
}

// ---------------------------------------------------------------------------
// RoPE tables + apply
// ---------------------------------------------------------------------------
__global__ void rope_tables_k() {
  int i = blockIdx.x * blockDim.x + threadIdx.x;  // S_*64
  if (i >= S_ * 64) return;
  int s = i >> 6, f = i & 63;
  double inv = exp(-((double)(2 * f) / 128.0) * log(10000.0));
  double ang = (double)s * inv;
  g_cos[i] = (float)cos(ang);
  g_sin[i] = (float)sin(ang);
}

__global__ void rope_apply_k() {
  int idx = blockIdx.x * blockDim.x + threadIdx.x;  // B*S*20*64
  if (idx >= B_ * S_ * (HEADS_ + GROUPS_) * 64) return;
  int f = idx & 63;
  int t = idx >> 6;
  int hh = t % (HEADS_ + GROUPS_);
  t /= (HEADS_ + GROUPS_);
  int s = t % S_;
  int b = t / S_;
  float c = g_cos[s * 64 + f];
  float sn = g_sin[s * 64 + f];
  float* base;
  if (hh < HEADS_) {
    base = g_q + ((size_t)((size_t)b * S_ + s) * HEADS_ + hh) * KVC_;
  } else {
    base = g_kv + (size_t)((size_t)b * S_ + s) * (2 * GROUPS_ * KVC_) +
           (hh - HEADS_) * KVC_;  // sel=0 (k)
  }
  float x1 = base[f];
  float x2 = base[f + 64];
  base[f] = x1 * c - x2 * sn;
  base[f + 64] = x2 * c + x1 * sn;
}

// ---------------------------------------------------------------------------
// Causal flash attention, fp32. BLOCK_M=64, BLOCK_N=64, D=128.
// ---------------------------------------------------------------------------
#define QT_ST 68
#define VS_ST 132
#define PS_ST 68
#define ATTN_SMEM ((128 * QT_ST * 2 + 64 * VS_ST + 64 * PS_ST) * 4)

__global__ __launch_bounds__(256) void attn64() {
  extern __shared__ float sm[];
  float* Qt = sm;                  // [128][QT_ST] q^T * scale
  float* Kt = Qt + 128 * QT_ST;    // [128][QT_ST] k^T
  float* Vs = Kt + 128 * QT_ST;    // [64][VS_ST]
  float* Ps = Vs + 64 * VS_ST;     // [64][PS_ST]
  const int qtile = blockIdx.x;
  const int b = blockIdx.y >> 4;
  const int h = blockIdx.y & 15;
  const int g = h >> 2;
  const int tid = threadIdx.x;
  const int tx = tid & 15, ty = tid >> 4;
  const int r0 = ty * 4, c0 = tx * 4;
  const float scale = 0.088388347648318447f;

  const float* Qg = g_q + ((size_t)((size_t)b * S_ + qtile * 64) * HEADS_ + h) * KVC_;
  for (int i = tid; i < 64 * 32; i += 256) {
    int r = i >> 5, d = (i & 31) * 4;
    float4 v = *(const float4*)(Qg + (size_t)r * (HEADS_ * KVC_) + d);
    Qt[(d + 0) * QT_ST + r] = v.x * scale;
    Qt[(d + 1) * QT_ST + r] = v.y * scale;
    Qt[(d + 2) * QT_ST + r] = v.z * scale;
    Qt[(d + 3) * QT_ST + r] = v.w * scale;
  }

  float m[4], l[4], O[4][8];
#pragma unroll
  for (int i = 0; i < 4; i++) {
    m[i] = -1e30f;
    l[i] = 0.f;
#pragma unroll
    for (int j = 0; j < 8; j++) O[i][j] = 0.f;
  }

  for (int jt = 0; jt <= qtile; jt++) {
    const float* Kg = g_kv + (size_t)((size_t)b * S_ + jt * 64) * (2 * GROUPS_ * KVC_) + g * KVC_;
    const float* Vg = Kg + GROUPS_ * KVC_;
    __syncthreads();
    for (int i = tid; i < 64 * 32; i += 256) {
      int r = i >> 5, d = (i & 31) * 4;
      float4 kv4 = *(const float4*)(Kg + (size_t)r * (2 * GROUPS_ * KVC_) + d);
      Kt[(d + 0) * QT_ST + r] = kv4.x;
      Kt[(d + 1) * QT_ST + r] = kv4.y;
      Kt[(d + 2) * QT_ST + r] = kv4.z;
      Kt[(d + 3) * QT_ST + r] = kv4.w;
      *(float4*)(Vs + r * VS_ST + d) =
          *(const float4*)(Vg + (size_t)r * (2 * GROUPS_ * KVC_) + d);
    }
    __syncthreads();

    float s[4][4];
#pragma unroll
    for (int i = 0; i < 4; i++)
#pragma unroll
      for (int j = 0; j < 4; j++) s[i][j] = 0.f;
#pragma unroll 4
    for (int kk = 0; kk < 128; kk++) {
      float4 a = *(const float4*)(Qt + kk * QT_ST + r0);
      float4 bb = *(const float4*)(Kt + kk * QT_ST + c0);
      float a4[4] = {a.x, a.y, a.z, a.w};
      float b4[4] = {bb.x, bb.y, bb.z, bb.w};
#pragma unroll
      for (int i = 0; i < 4; i++)
#pragma unroll
        for (int j = 0; j < 4; j++) s[i][j] += a4[i] * b4[j];
    }
    if (jt == qtile) {
#pragma unroll
      for (int i = 0; i < 4; i++)
#pragma unroll
        for (int j = 0; j < 4; j++)
          if (c0 + j > r0 + i) s[i][j] = -1e30f;
    }

    float rm[4];
#pragma unroll
    for (int i = 0; i < 4; i++)
      rm[i] = fmaxf(fmaxf(s[i][0], s[i][1]), fmaxf(s[i][2], s[i][3]));
#pragma unroll
    for (int off = 1; off < 16; off <<= 1)
#pragma unroll
      for (int i = 0; i < 4; i++)
        rm[i] = fmaxf(rm[i], __shfl_xor_sync(0xffffffffu, rm[i], off));

    float rs[4];
#pragma unroll
    for (int i = 0; i < 4; i++) {
      float mn = fmaxf(m[i], rm[i]);
      float al = expf(m[i] - mn);
      float p0 = expf(s[i][0] - mn);
      float p1 = expf(s[i][1] - mn);
      float p2 = expf(s[i][2] - mn);
      float p3 = expf(s[i][3] - mn);
      Ps[(r0 + i) * PS_ST + c0 + 0] = p0;
      Ps[(r0 + i) * PS_ST + c0 + 1] = p1;
      Ps[(r0 + i) * PS_ST + c0 + 2] = p2;
      Ps[(r0 + i) * PS_ST + c0 + 3] = p3;
      rs[i] = p0 + p1 + p2 + p3;
      l[i] = l[i] * al;
      m[i] = mn;
#pragma unroll
      for (int j = 0; j < 8; j++) O[i][j] *= al;
    }
#pragma unroll
    for (int off = 1; off < 16; off <<= 1)
#pragma unroll
      for (int i = 0; i < 4; i++)
        rs[i] += __shfl_xor_sync(0xffffffffu, rs[i], off);
#pragma unroll
    for (int i = 0; i < 4; i++) l[i] += rs[i];
    __syncthreads();

#pragma unroll 2
    for (int c = 0; c < 64; c++) {
      float pv[4];
#pragma unroll
      for (int i = 0; i < 4; i++) pv[i] = Ps[(r0 + i) * PS_ST + c];
#pragma unroll
      for (int j = 0; j < 8; j++) {
        float vv = Vs[c * VS_ST + j * 16 + tx];
#pragma unroll
        for (int i = 0; i < 4; i++) O[i][j] += pv[i] * vv;
      }
    }
  }

#pragma unroll
  for (int i = 0; i < 4; i++) {
    float inv = 1.f / l[i];
    size_t row = (size_t)b * S_ + qtile * 64 + r0 + i;
    float* crow = g_ctx + (row * HEADS_ + h) * KVC_;
#pragma unroll
    for (int j = 0; j < 8; j++) crow[j * 16 + tx] = O[i][j] * inv;
  }
}

// ---------------------------------------------------------------------------
extern "C" void kernel_launch(void* const* d_in, const int* in_sizes, int n_in,
                              void* d_out, int out_size) {
  (void)in_sizes; (void)n_in; (void)out_size;
  const float* x = (const float*)d_in[0];
  const float* w_q = (const float*)d_in[1];
  const float* w_kv = (const float*)d_in[2];
  const float* w_dense = (const float*)d_in[3];
  float* out = (float*)d_out;

  float *qb, *kvb, *ctxb;
  cudaGetSymbolAddress((void**)&qb, g_q);
  cudaGetSymbolAddress((void**)&kvb, g_kv);
  cudaGetSymbolAddress((void**)&ctxb, g_ctx);

  cudaFuncSetAttribute(attn64, cudaFuncAttributeMaxDynamicSharedMemorySize,
                       ATTN_SMEM);

  const int M = B_ * S_;  // 4096
  // 1) QKV projections (tf32 tensor cores)
  tf32gemm<<<dim3((HEADS_ * KVC_) / 128, M / 128), 256>>>(
      M, HEADS_ * KVC_, HID_, x, w_q, qb);
  tf32gemm<<<dim3((2 * GROUPS_ * KVC_) / 128, M / 128), 256>>>(
      M, 2 * GROUPS_ * KVC_, HID_, x, w_kv, kvb);
  // 2) RoPE
  rope_tables_k<<<(S_ * 64 + 255) / 256, 256>>>();
  rope_apply_k<<<(B_ * S_ * (HEADS_ + GROUPS_) * 64 + 255) / 256, 256>>>();
  // 3) causal GQA flash attention (fp32)
  attn64<<<dim3(S_ / 64, B_ * HEADS_), 256, ATTN_SMEM>>>();
  // 4) dense projection -> out (tf32 tensor cores)
  tf32gemm<<<dim3(HID_ / 128, M / 128), 256>>>(M, HID_, HEADS_ * KVC_, ctxb,
                                               w_dense, out);
}

// round 6
// speedup vs baseline: 2.8166x; 1.7806x over previous
#include <cuda_runtime.h>
#include <math.h>
#include <stdint.h>

#define B_ 2
#define S_ 2048
#define HID_ 2048
#define HEADS_ 16
#define GROUPS_ 4
#define KVC_ 128
// scratch (device globals: no allocs allowed)
__device__ float g_q[(size_t)B_ * S_ * HEADS_ * KVC_];        // [b,s,h,d]
__device__ float g_kv[(size_t)B_ * S_ * 2 * GROUPS_ * KVC_];  // [b,s,sel,g,d]
__device__ float g_ctx[(size_t)B_ * S_ * HEADS_ * KVC_];      // [b,s,h,d]
__device__ float g_cos[S_ * 64];
__device__ float g_sin[S_ * 64];

// ---------------------------------------------------------------------------
// tf32 helpers
// ---------------------------------------------------------------------------
__device__ __forceinline__ uint32_t f2tf32(float x) {
  uint32_t r;
  asm("cvt.rna.tf32.f32 %0, %1;" : "=r"(r) : "f"(x));
  return r;
}
__device__ __forceinline__ float ex2f(float x) {
  float y;
  asm("ex2.approx.ftz.f32 %0, %1;" : "=f"(y) : "f"(x));
  return y;
}
__device__ __forceinline__ void mma_tf32(float c[4], const uint32_t a[4],
                                         const uint32_t b[2]) {
  asm volatile(
      "mma.sync.aligned.m16n8k8.row.col.f32.tf32.tf32.f32 "
      "{%0,%1,%2,%3}, {%4,%5,%6,%7}, {%8,%9}, {%0,%1,%2,%3};\n"
      : "+f"(c[0]), "+f"(c[1]), "+f"(c[2]), "+f"(c[3])
      : "r"(a[0]), "r"(a[1]), "r"(a[2]), "r"(a[3]), "r"(b[0]), "r"(b[1]));
}

// ---------------------------------------------------------------------------
// tf32 tensor-core GEMM: C[M,N] = A[M,K] @ B[K,N], all row-major.
// Block 128x128, K-chunk 32, 256 threads = 8 warps in 4x2 grid,
// warp tile 32x64. Register-staged prefetch hides global-load latency.
// ---------------------------------------------------------------------------
__global__ __launch_bounds__(256) void tf32gemm(
    int M, int N, int K,
    const float* __restrict__ A, const float* __restrict__ B,
    float* __restrict__ C) {
  __shared__ uint32_t As[128][36];
  __shared__ uint32_t Bs[32][132];
  const int tid = threadIdx.x;
  const int lane = tid & 31;
  const int wid = tid >> 5;
  const int gid = lane >> 2;
  const int tig = lane & 3;
  const int wr = wid >> 1;
  const int wc = wid & 1;
  const size_t rb = (size_t)blockIdx.y * 128;
  const int cb = blockIdx.x * 128;

  // per-thread global addresses (fixed across chunks, advance by k)
  const int ar = tid >> 1;           // A row 0..127 (2 threads per row)
  const int ac = (tid & 1) * 16;     // A col base: 16 floats (4 float4) each
  const int br = tid >> 5;           // B row 0..7 (x4 iterations -> +8)
  const int bc = (tid & 31) * 4;     // B col

  float acc[2][8][4];
#pragma unroll
  for (int mt = 0; mt < 2; mt++)
#pragma unroll
    for (int nt = 0; nt < 8; nt++)
#pragma unroll
      for (int i = 0; i < 4; i++) acc[mt][nt][i] = 0.f;

  const int arow0 = wr * 32 + gid;
  const int bcol0 = wc * 64 + gid;

  // prefetch chunk 0 into registers (A: 4 float4 = 16 cols; B: 4 float4)
  float4 pa[4], pb[4];
#pragma unroll
  for (int it = 0; it < 4; it++)
    pa[it] = *(const float4*)(A + (rb + ar) * K + ac + it * 4);
#pragma unroll
  for (int it = 0; it < 4; it++)
    pb[it] = *(const float4*)(B + (size_t)(br + it * 8) * N + cb + bc);

  for (int k0 = 0; k0 < K; k0 += 32) {
    // ---- store prefetched regs to smem (converted to tf32) ----
#pragma unroll
    for (int it = 0; it < 4; it++) {
      uint4 u = make_uint4(f2tf32(pa[it].x), f2tf32(pa[it].y),
                           f2tf32(pa[it].z), f2tf32(pa[it].w));
      *(uint4*)&As[ar][ac + it * 4] = u;
    }
#pragma unroll
    for (int it = 0; it < 4; it++) {
      uint4 u = make_uint4(f2tf32(pb[it].x), f2tf32(pb[it].y),
                           f2tf32(pb[it].z), f2tf32(pb[it].w));
      *(uint4*)&Bs[br + it * 8][bc] = u;
    }
    __syncthreads();

    // ---- prefetch next chunk (overlaps with MMA below) ----
    if (k0 + 32 < K) {
      int kn = k0 + 32;
#pragma unroll
      for (int it = 0; it < 4; it++)
        pa[it] = *(const float4*)(A + (rb + ar) * K + kn + ac + it * 4);
#pragma unroll
      for (int it = 0; it < 4; it++)
        pb[it] = *(const float4*)(B + (size_t)(kn + br + it * 8) * N + cb + bc);
    }

    // ---- MMA over current smem chunk ----
#pragma unroll
    for (int kk = 0; kk < 32; kk += 8) {
      uint32_t af[2][4], bf[8][2];
#pragma unroll
      for (int mt = 0; mt < 2; mt++) {
        int r = arow0 + mt * 16;
        af[mt][0] = As[r][kk + tig];
        af[mt][1] = As[r + 8][kk + tig];
        af[mt][2] = As[r][kk + tig + 4];
        af[mt][3] = As[r + 8][kk + tig + 4];
      }
#pragma unroll
      for (int nt = 0; nt < 8; nt++) {
        int c = bcol0 + nt * 8;
        bf[nt][0] = Bs[kk + tig][c];
        bf[nt][1] = Bs[kk + tig + 4][c];
      }
#pragma unroll
      for (int mt = 0; mt < 2; mt++)
#pragma unroll
        for (int nt = 0; nt < 8; nt++) mma_tf32(acc[mt][nt], af[mt], bf[nt]);
    }
    __syncthreads();
  }

#pragma unroll
  for (int mt = 0; mt < 2; mt++) {
#pragma unroll
    for (int nt = 0; nt < 8; nt++) {
      size_t r0 = rb + wr * 32 + mt * 16 + gid;
      int c = cb + wc * 64 + nt * 8 + tig * 2;
      float2 lo = make_float2(acc[mt][nt][0], acc[mt][nt][1]);
      float2 hi = make_float2(acc[mt][nt][2], acc[mt][nt][3]);
      *(float2*)&C[r0 * N + c] = lo;
      *(float2*)&C[(r0 + 8) * N + c] = hi;
    }
  }
}

// ---------------------------------------------------------------------------
// RoPE tables + apply
// ---------------------------------------------------------------------------
__global__ void rope_tables_k() {
  int i = blockIdx.x * blockDim.x + threadIdx.x;
  if (i >= S_ * 64) return;
  int s = i >> 6, f = i & 63;
  double inv = exp(-((double)(2 * f) / 128.0) * log(10000.0));
  double ang = (double)s * inv;
  g_cos[i] = (float)cos(ang);
  g_sin[i] = (float)sin(ang);
}

__global__ void rope_apply_k() {
  int idx = blockIdx.x * blockDim.x + threadIdx.x;
  if (idx >= B_ * S_ * (HEADS_ + GROUPS_) * 64) return;
  int f = idx & 63;
  int t = idx >> 6;
  int hh = t % (HEADS_ + GROUPS_);
  t /= (HEADS_ + GROUPS_);
  int s = t % S_;
  int b = t / S_;
  float c = g_cos[s * 64 + f];
  float sn = g_sin[s * 64 + f];
  float* base;
  if (hh < HEADS_) {
    base = g_q + ((size_t)((size_t)b * S_ + s) * HEADS_ + hh) * KVC_;
  } else {
    base = g_kv + (size_t)((size_t)b * S_ + s) * (2 * GROUPS_ * KVC_) +
           (hh - HEADS_) * KVC_;
  }
  float x1 = base[f];
  float x2 = base[f + 64];
  base[f] = x1 * c - x2 * sn;
  base[f + 64] = x2 * c + x1 * sn;
}

// ---------------------------------------------------------------------------
// Tensor-core causal flash attention. BLOCK_M=128, BLOCK_N=64, D=128.
// 8 warps, each owns a 16-row strip. S = Q*(Khi+Klo) (2 mmas, Q pre-scaled
// by softmax_scale*log2e), online softmax in log2 domain, PV plain tf32.
// ---------------------------------------------------------------------------
#define QS_ST 132  // % 32 words = 4 -> conflict-free A/B frag patterns
#define KS_ST 132
#define VS_ST2 136  // % 32 = 8 -> conflict-free for V B-frag pattern
#define PS_ST2 68   // % 32 = 4
#define QS_WORDS (128 * QS_ST)
#define KH_WORDS (64 * KS_ST)
#define VS_WORDS (64 * VS_ST2)
#define PS_WORDS (128 * PS_ST2)
#define ATTN2_SMEM ((QS_WORDS + 2 * KH_WORDS + VS_WORDS + PS_WORDS) * 4)

__global__ __launch_bounds__(256, 1) void attn_tc() {
  extern __shared__ uint32_t smw[];
  uint32_t* Qs = smw;
  uint32_t* KH = Qs + QS_WORDS;
  uint32_t* KL = KH + KH_WORDS;
  uint32_t* Vs = KL + KH_WORDS;
  uint32_t* Ps = Vs + VS_WORDS;

  const int qt = 15 - blockIdx.x;  // big tiles first (load balance)
  const int b = blockIdx.y >> 4;
  const int h = blockIdx.y & 15;
  const int g = h >> 2;
  const int tid = threadIdx.x;
  const int lane = tid & 31;
  const int wid = tid >> 5;
  const int gid = lane >> 2;
  const int tig = lane & 3;
  const int rbase = wid * 16;  // warp's row strip within the 128-row block

  // softmax_scale * log2(e): scores land directly in log2 domain
  const float qscale = 0.088388347648318447f * 1.4426950408889634f;

  // ---- load Q tile 128x128 -> tf32 (pre-scaled) ----
  const float* Qg =
      g_q + ((size_t)((size_t)b * S_ + qt * 128) * HEADS_ + h) * KVC_;
  for (int i = tid; i < 128 * 32; i += 256) {
    int r = i >> 5, d4 = (i & 31) * 4;
    float4 v = *(const float4*)(Qg + (size_t)r * (HEADS_ * KVC_) + d4);
    uint4 u = make_uint4(f2tf32(v.x * qscale), f2tf32(v.y * qscale),
                         f2tf32(v.z * qscale), f2tf32(v.w * qscale));
    *(uint4*)&Qs[r * QS_ST + d4] = u;
  }

  float m0 = -1e30f, m1 = -1e30f, l0 = 0.f, l1 = 0.f;
  float O[16][4];
#pragma unroll
  for (int nt = 0; nt < 16; nt++)
#pragma unroll
    for (int i = 0; i < 4; i++) O[nt][i] = 0.f;

  const int jmax = 2 * qt + 1;
  for (int jt = 0; jt <= jmax; jt++) {
    __syncthreads();  // previous iter's K/V reads complete
    // ---- load K (hi/lo split) and V (tf32) tiles 64x128 ----
    const float* Kg =
        g_kv + (size_t)((size_t)b * S_ + jt * 64) * (2 * GROUPS_ * KVC_) +
        g * KVC_;
    for (int i = tid; i < 64 * 32; i += 256) {
      int r = i >> 5, d4 = (i & 31) * 4;
      float4 kv = *(const float4*)(Kg + (size_t)r * (2 * GROUPS_ * KVC_) + d4);
      uint4 hi, lo;
      hi.x = f2tf32(kv.x); lo.x = f2tf32(kv.x - __uint_as_float(hi.x));
      hi.y = f2tf32(kv.y); lo.y = f2tf32(kv.y - __uint_as_float(hi.y));
      hi.z = f2tf32(kv.z); lo.z = f2tf32(kv.z - __uint_as_float(hi.z));
      hi.w = f2tf32(kv.w); lo.w = f2tf32(kv.w - __uint_as_float(hi.w));
      *(uint4*)&KH[r * KS_ST + d4] = hi;
      *(uint4*)&KL[r * KS_ST + d4] = lo;
      float4 vv = *(const float4*)(Kg + GROUPS_ * KVC_ +
                                   (size_t)r * (2 * GROUPS_ * KVC_) + d4);
      uint4 uv = make_uint4(f2tf32(vv.x), f2tf32(vv.y), f2tf32(vv.z),
                            f2tf32(vv.w));
      *(uint4*)&Vs[r * VS_ST2 + d4] = uv;
    }
    __syncthreads();

    // warp strip fully masked for this kv tile? (still hit the syncs above)
    bool active = (jt * 64) <= (qt * 128 + rbase + 15);
    if (active) {
      // ---- S = Q @ K^T (hi + lo) ----
      float sacc[8][4];
#pragma unroll
      for (int nt = 0; nt < 8; nt++)
#pragma unroll
        for (int i = 0; i < 4; i++) sacc[nt][i] = 0.f;

#pragma unroll 2
      for (int kk = 0; kk < 128; kk += 8) {
        uint32_t a[4];
        int ra = (rbase + gid) * QS_ST + kk + tig;
        a[0] = Qs[ra];
        a[1] = Qs[ra + 8 * QS_ST];
        a[2] = Qs[ra + 4];
        a[3] = Qs[ra + 8 * QS_ST + 4];
#pragma unroll
        for (int nt = 0; nt < 8; nt++) {
          int rk = (nt * 8 + gid) * KS_ST + kk + tig;
          uint32_t bh[2] = {KH[rk], KH[rk + 4]};
          uint32_t bl[2] = {KL[rk], KL[rk + 4]};
          mma_tf32(sacc[nt], a, bh);
          mma_tf32(sacc[nt], a, bl);
        }
      }

      // ---- causal mask (only when tile touches the diagonal) ----
      int rowg0 = qt * 128 + rbase + gid;
      int rowg1 = rowg0 + 8;
      if (jt * 64 + 63 > rowg0) {
#pragma unroll
        for (int nt = 0; nt < 8; nt++) {
          int colg = jt * 64 + nt * 8 + 2 * tig;
          if (colg > rowg0) sacc[nt][0] = -1e30f;
          if (colg + 1 > rowg0) sacc[nt][1] = -1e30f;
          if (colg > rowg1) sacc[nt][2] = -1e30f;
          if (colg + 1 > rowg1) sacc[nt][3] = -1e30f;
        }
      }

      // ---- online softmax (log2 domain), rows gid / gid+8 ----
      float rm0 = -1e30f, rm1 = -1e30f;
#pragma unroll
      for (int nt = 0; nt < 8; nt++) {
        rm0 = fmaxf(rm0, fmaxf(sacc[nt][0], sacc[nt][1]));
        rm1 = fmaxf(rm1, fmaxf(sacc[nt][2], sacc[nt][3]));
      }
      rm0 = fmaxf(rm0, __shfl_xor_sync(0xffffffffu, rm0, 1));
      rm0 = fmaxf(rm0, __shfl_xor_sync(0xffffffffu, rm0, 2));
      rm1 = fmaxf(rm1, __shfl_xor_sync(0xffffffffu, rm1, 1));
      rm1 = fmaxf(rm1, __shfl_xor_sync(0xffffffffu, rm1, 2));

      float mn0 = fmaxf(m0, rm0), mn1 = fmaxf(m1, rm1);
      float al0 = ex2f(m0 - mn0), al1 = ex2f(m1 - mn1);
      m0 = mn0; m1 = mn1;

      float rs0 = 0.f, rs1 = 0.f;
#pragma unroll
      for (int nt = 0; nt < 8; nt++) {
        float p0 = ex2f(sacc[nt][0] - mn0);
        float p1 = ex2f(sacc[nt][1] - mn0);
        float p2 = ex2f(sacc[nt][2] - mn1);
        float p3 = ex2f(sacc[nt][3] - mn1);
        rs0 += p0 + p1;
        rs1 += p2 + p3;
        uint2 w01 = make_uint2(f2tf32(p0), f2tf32(p1));
        uint2 w23 = make_uint2(f2tf32(p2), f2tf32(p3));
        int c = nt * 8 + 2 * tig;
        *(uint2*)&Ps[(rbase + gid) * PS_ST2 + c] = w01;
        *(uint2*)&Ps[(rbase + gid + 8) * PS_ST2 + c] = w23;
      }
      rs0 += __shfl_xor_sync(0xffffffffu, rs0, 1);
      rs0 += __shfl_xor_sync(0xffffffffu, rs0, 2);
      rs1 += __shfl_xor_sync(0xffffffffu, rs1, 1);
      rs1 += __shfl_xor_sync(0xffffffffu, rs1, 2);
      l0 = l0 * al0 + rs0;
      l1 = l1 * al1 + rs1;

#pragma unroll
      for (int nt = 0; nt < 16; nt++) {
        O[nt][0] *= al0;
        O[nt][1] *= al0;
        O[nt][2] *= al1;
        O[nt][3] *= al1;
      }
      __syncwarp();  // Ps stores visible to this warp's fragment loads

      // ---- O += P @ V ----
#pragma unroll 2
      for (int kk = 0; kk < 64; kk += 8) {
        uint32_t a[4];
        int rp = (rbase + gid) * PS_ST2 + kk + tig;
        a[0] = Ps[rp];
        a[1] = Ps[rp + 8 * PS_ST2];
        a[2] = Ps[rp + 4];
        a[3] = Ps[rp + 8 * PS_ST2 + 4];
#pragma unroll
        for (int nt = 0; nt < 16; nt++) {
          int rv = (kk + tig) * VS_ST2 + nt * 8 + gid;
          uint32_t bv[2] = {Vs[rv], Vs[rv + 4 * VS_ST2]};
          mma_tf32(O[nt], a, bv);
        }
      }
    }
  }

  // ---- epilogue: normalize + write ctx ----
  float inv0 = 1.f / l0, inv1 = 1.f / l1;
  size_t row0 = (size_t)b * S_ + qt * 128 + rbase + gid;
  float* c0 = g_ctx + (row0 * HEADS_ + h) * KVC_;
  float* c1 = g_ctx + ((row0 + 8) * HEADS_ + h) * KVC_;
#pragma unroll
  for (int nt = 0; nt < 16; nt++) {
    int c = nt * 8 + 2 * tig;
    *(float2*)&c0[c] = make_float2(O[nt][0] * inv0, O[nt][1] * inv0);
    *(float2*)&c1[c] = make_float2(O[nt][2] * inv1, O[nt][3] * inv1);
  }
}

// ---------------------------------------------------------------------------
extern "C" void kernel_launch(void* const* d_in, const int* in_sizes, int n_in,
                              void* d_out, int out_size) {
  (void)in_sizes; (void)n_in; (void)out_size;
  const float* x = (const float*)d_in[0];
  const float* w_q = (const float*)d_in[1];
  const float* w_kv = (const float*)d_in[2];
  const float* w_dense = (const float*)d_in[3];
  float* out = (float*)d_out;

  float *qb, *kvb, *ctxb;
  cudaGetSymbolAddress((void**)&qb, g_q);
  cudaGetSymbolAddress((void**)&kvb, g_kv);
  cudaGetSymbolAddress((void**)&ctxb, g_ctx);

  cudaFuncSetAttribute(attn_tc, cudaFuncAttributeMaxDynamicSharedMemorySize,
                       ATTN2_SMEM);

  const int M = B_ * S_;  // 4096
  // 1) QKV projections (tf32 tensor cores, prefetched)
  tf32gemm<<<dim3((HEADS_ * KVC_) / 128, M / 128), 256>>>(
      M, HEADS_ * KVC_, HID_, x, w_q, qb);
  tf32gemm<<<dim3((2 * GROUPS_ * KVC_) / 128, M / 128), 256>>>(
      M, 2 * GROUPS_ * KVC_, HID_, x, w_kv, kvb);
  // 2) RoPE
  rope_tables_k<<<(S_ * 64 + 255) / 256, 256>>>();
  rope_apply_k<<<(B_ * S_ * (HEADS_ + GROUPS_) * 64 + 255) / 256, 256>>>();
  // 3) causal GQA flash attention (tensor cores)
  attn_tc<<<dim3(S_ / 128, B_ * HEADS_), 256, ATTN2_SMEM>>>();
  // 4) dense projection -> out (tf32 tensor cores, prefetched)
  tf32gemm<<<dim3(HID_ / 128, M / 128), 256>>>(M, HID_, HEADS_ * KVC_, ctxb,
                                               w_dense, out);
}

// round 12
// speedup vs baseline: 2.9148x; 1.0349x over previous
#include <cuda_runtime.h>
#include <math.h>
#include <stdint.h>

#define B_ 2
#define S_ 2048
#define HID_ 2048
#define HEADS_ 16
#define GROUPS_ 4
#define KVC_ 128
// scratch (device globals: no allocs allowed)
__device__ float g_q[(size_t)B_ * S_ * HEADS_ * KVC_];        // [b,s,h,d]
__device__ float g_kv[(size_t)B_ * S_ * 2 * GROUPS_ * KVC_];  // [b,s,sel,g,d]
__device__ float g_ctx[(size_t)B_ * S_ * HEADS_ * KVC_];      // [b,s,h,d]
__device__ float g_cos[S_ * 64];
__device__ float g_sin[S_ * 64];

// ---------------------------------------------------------------------------
// tf32 helpers
// ---------------------------------------------------------------------------
__device__ __forceinline__ uint32_t f2tf32(float x) {
  uint32_t r;
  asm("cvt.rna.tf32.f32 %0, %1;" : "=r"(r) : "f"(x));
  return r;
}
__device__ __forceinline__ float ex2f(float x) {
  float y;
  asm("ex2.approx.ftz.f32 %0, %1;" : "=f"(y) : "f"(x));
  return y;
}
__device__ __forceinline__ void mma_tf32(float c[4], const uint32_t a[4],
                                         const uint32_t b[2]) {
  asm volatile(
      "mma.sync.aligned.m16n8k8.row.col.f32.tf32.tf32.f32 "
      "{%0,%1,%2,%3}, {%4,%5,%6,%7}, {%8,%9}, {%0,%1,%2,%3};\n"
      : "+f"(c[0]), "+f"(c[1]), "+f"(c[2]), "+f"(c[3])
      : "r"(a[0]), "r"(a[1]), "r"(a[2]), "r"(a[3]), "r"(b[0]), "r"(b[1]));
}

// ---------------------------------------------------------------------------
// tf32 tensor-core GEMM, double-buffered smem, one sync per K-chunk.
// Dual-output: block columns [0, N0/128) compute A@B0 -> C0,
//              block columns [N0/128, ..) compute A@B1 -> C1.
// Block 128x128, K-chunk 32, 256 threads, warp tile 32x64.
// Dynamic smem: 2 stages x (As[128][36] + Bs[32][132]) words.
// ---------------------------------------------------------------------------
#define GA_WORDS (128 * 36)
#define GB_WORDS (32 * 132)
#define GSTAGE_WORDS (GA_WORDS + GB_WORDS)
#define GEMM_SMEM (2 * GSTAGE_WORDS * 4)

__global__ __launch_bounds__(256, 2) void tf32gemm2(
    int K, const float* __restrict__ A,
    const float* __restrict__ B0, int N0, float* __restrict__ C0,
    const float* __restrict__ B1, int N1, float* __restrict__ C1) {
  extern __shared__ uint32_t dsm[];
  const int tid = threadIdx.x;
  const int lane = tid & 31;
  const int wid = tid >> 5;
  const int gid = lane >> 2;
  const int tig = lane & 3;
  const int wr = wid >> 1;
  const int wc = wid & 1;
  const size_t rb = (size_t)blockIdx.y * 128;

  // select output matrix by block column
  const int nb0 = N0 >> 7;
  const float* Bm;
  float* Cm;
  int N, cb;
  if ((int)blockIdx.x < nb0) {
    Bm = B0; Cm = C0; N = N0; cb = blockIdx.x * 128;
  } else {
    Bm = B1; Cm = C1; N = N1; cb = (blockIdx.x - nb0) * 128;
  }

  // per-thread load coords
  const int ar = tid >> 1;        // A row (2 threads/row)
  const int ac = (tid & 1) * 16;  // A col base (16 floats)
  const int br = tid >> 5;        // B row base (+8 per it)
  const int bc = (tid & 31) * 4;  // B col

  float acc[2][8][4];
#pragma unroll
  for (int mt = 0; mt < 2; mt++)
#pragma unroll
    for (int nt = 0; nt < 8; nt++)
#pragma unroll
      for (int i = 0; i < 4; i++) acc[mt][nt][i] = 0.f;

  const int arow0 = wr * 32 + gid;
  const int bcol0 = wc * 64 + gid;

  // prefetch chunk 0
  float4 pa[4], pb[4];
#pragma unroll
  for (int it = 0; it < 4; it++)
    pa[it] = *(const float4*)(A + (rb + ar) * K + ac + it * 4);
#pragma unroll
  for (int it = 0; it < 4; it++)
    pb[it] = *(const float4*)(Bm + (size_t)(br + it * 8) * N + cb + bc);

  int stage = 0;
  for (int k0 = 0; k0 < K; k0 += 32) {
    uint32_t* As = dsm + stage * GSTAGE_WORDS;          // [128][36]
    uint32_t* Bs = As + GA_WORDS;                       // [32][132]
    // ---- store prefetched regs to this stage ----
#pragma unroll
    for (int it = 0; it < 4; it++) {
      uint4 u = make_uint4(f2tf32(pa[it].x), f2tf32(pa[it].y),
                           f2tf32(pa[it].z), f2tf32(pa[it].w));
      *(uint4*)&As[ar * 36 + ac + it * 4] = u;
    }
#pragma unroll
    for (int it = 0; it < 4; it++) {
      uint4 u = make_uint4(f2tf32(pb[it].x), f2tf32(pb[it].y),
                           f2tf32(pb[it].z), f2tf32(pb[it].w));
      *(uint4*)&Bs[(br + it * 8) * 132 + bc] = u;
    }
    __syncthreads();  // stage ready; also fences prior stage's MMA readers

    // ---- prefetch next chunk (overlaps MMA below) ----
    if (k0 + 32 < K) {
      int kn = k0 + 32;
#pragma unroll
      for (int it = 0; it < 4; it++)
        pa[it] = *(const float4*)(A + (rb + ar) * K + kn + ac + it * 4);
#pragma unroll
      for (int it = 0; it < 4; it++)
        pb[it] =
            *(const float4*)(Bm + (size_t)(kn + br + it * 8) * N + cb + bc);
    }

    // ---- MMA over current stage ----
#pragma unroll
    for (int kk = 0; kk < 32; kk += 8) {
      uint32_t af[2][4], bf[8][2];
#pragma unroll
      for (int mt = 0; mt < 2; mt++) {
        int r = arow0 + mt * 16;
        af[mt][0] = As[r * 36 + kk + tig];
        af[mt][1] = As[(r + 8) * 36 + kk + tig];
        af[mt][2] = As[r * 36 + kk + tig + 4];
        af[mt][3] = As[(r + 8) * 36 + kk + tig + 4];
      }
#pragma unroll
      for (int nt = 0; nt < 8; nt++) {
        int c = bcol0 + nt * 8;
        bf[nt][0] = Bs[(kk + tig) * 132 + c];
        bf[nt][1] = Bs[(kk + tig + 4) * 132 + c];
      }
#pragma unroll
      for (int mt = 0; mt < 2; mt++)
#pragma unroll
        for (int nt = 0; nt < 8; nt++) mma_tf32(acc[mt][nt], af[mt], bf[nt]);
    }
    stage ^= 1;  // next chunk writes the other buffer (no tail sync needed)
  }

#pragma unroll
  for (int mt = 0; mt < 2; mt++) {
#pragma unroll
    for (int nt = 0; nt < 8; nt++) {
      size_t r0 = rb + wr * 32 + mt * 16 + gid;
      int c = cb + wc * 64 + nt * 8 + tig * 2;
      float2 lo = make_float2(acc[mt][nt][0], acc[mt][nt][1]);
      float2 hi = make_float2(acc[mt][nt][2], acc[mt][nt][3]);
      *(float2*)&Cm[r0 * N + c] = lo;
      *(float2*)&Cm[(r0 + 8) * N + c] = hi;
    }
  }
}

// ---------------------------------------------------------------------------
// RoPE tables + apply
// ---------------------------------------------------------------------------
__global__ void rope_tables_k() {
  int i = blockIdx.x * blockDim.x + threadIdx.x;
  if (i >= S_ * 64) return;
  int s = i >> 6, f = i & 63;
  double inv = exp(-((double)(2 * f) / 128.0) * log(10000.0));
  double ang = (double)s * inv;
  g_cos[i] = (float)cos(ang);
  g_sin[i] = (float)sin(ang);
}

__global__ void rope_apply_k() {
  int idx = blockIdx.x * blockDim.x + threadIdx.x;
  if (idx >= B_ * S_ * (HEADS_ + GROUPS_) * 64) return;
  int f = idx & 63;
  int t = idx >> 6;
  int hh = t % (HEADS_ + GROUPS_);
  t /= (HEADS_ + GROUPS_);
  int s = t % S_;
  int b = t / S_;
  float c = g_cos[s * 64 + f];
  float sn = g_sin[s * 64 + f];
  float* base;
  if (hh < HEADS_) {
    base = g_q + ((size_t)((size_t)b * S_ + s) * HEADS_ + hh) * KVC_;
  } else {
    base = g_kv + (size_t)((size_t)b * S_ + s) * (2 * GROUPS_ * KVC_) +
           (hh - HEADS_) * KVC_;
  }
  float x1 = base[f];
  float x2 = base[f + 64];
  base[f] = x1 * c - x2 * sn;
  base[f + 64] = x2 * c + x1 * sn;
}

// ---------------------------------------------------------------------------
// Tensor-core causal flash attention. BLOCK_M=128, BLOCK_N=64, D=128.
// 8 warps, each owns a 16-row strip. S = Q*(Khi+Klo) (2 mmas, Q pre-scaled
// by softmax_scale*log2e), online softmax in log2 domain, PV plain tf32.
// ---------------------------------------------------------------------------
#define QS_ST 132  // % 32 words = 4 -> conflict-free A/B frag patterns
#define KS_ST 132
#define VS_ST2 136  // % 32 = 8 -> conflict-free for V B-frag pattern
#define PS_ST2 68   // % 32 = 4
#define QS_WORDS (128 * QS_ST)
#define KH_WORDS (64 * KS_ST)
#define VS_WORDS (64 * VS_ST2)
#define PS_WORDS (128 * PS_ST2)
#define ATTN2_SMEM ((QS_WORDS + 2 * KH_WORDS + VS_WORDS + PS_WORDS) * 4)

__global__ __launch_bounds__(256, 1) void attn_tc() {
  extern __shared__ uint32_t smw[];
  uint32_t* Qs = smw;
  uint32_t* KH = Qs + QS_WORDS;
  uint32_t* KL = KH + KH_WORDS;
  uint32_t* Vs = KL + KH_WORDS;
  uint32_t* Ps = Vs + VS_WORDS;

  const int qt = 15 - blockIdx.x;  // big tiles first (load balance)
  const int b = blockIdx.y >> 4;
  const int h = blockIdx.y & 15;
  const int g = h >> 2;
  const int tid = threadIdx.x;
  const int lane = tid & 31;
  const int wid = tid >> 5;
  const int gid = lane >> 2;
  const int tig = lane & 3;
  const int rbase = wid * 16;  // warp's row strip within the 128-row block

  // softmax_scale * log2(e): scores land directly in log2 domain
  const float qscale = 0.088388347648318447f * 1.4426950408889634f;

  // ---- load Q tile 128x128 -> tf32 (pre-scaled) ----
  const float* Qg =
      g_q + ((size_t)((size_t)b * S_ + qt * 128) * HEADS_ + h) * KVC_;
  for (int i = tid; i < 128 * 32; i += 256) {
    int r = i >> 5, d4 = (i & 31) * 4;
    float4 v = *(const float4*)(Qg + (size_t)r * (HEADS_ * KVC_) + d4);
    uint4 u = make_uint4(f2tf32(v.x * qscale), f2tf32(v.y * qscale),
                         f2tf32(v.z * qscale), f2tf32(v.w * qscale));
    *(uint4*)&Qs[r * QS_ST + d4] = u;
  }

  float m0 = -1e30f, m1 = -1e30f, l0 = 0.f, l1 = 0.f;
  float O[16][4];
#pragma unroll
  for (int nt = 0; nt < 16; nt++)
#pragma unroll
    for (int i = 0; i < 4; i++) O[nt][i] = 0.f;

  const int jmax = 2 * qt + 1;
  for (int jt = 0; jt <= jmax; jt++) {
    __syncthreads();  // previous iter done reading K/V/P
    // ---- load K (hi/lo split) and V (tf32) tiles 64x128 ----
    const float* Kg =
        g_kv + (size_t)((size_t)b * S_ + jt * 64) * (2 * GROUPS_ * KVC_) +
        g * KVC_;
    for (int i = tid; i < 64 * 32; i += 256) {
      int r = i >> 5, d4 = (i & 31) * 4;
      float4 kv = *(const float4*)(Kg + (size_t)r * (2 * GROUPS_ * KVC_) + d4);
      uint4 hi, lo;
      hi.x = f2tf32(kv.x); lo.x = f2tf32(kv.x - __uint_as_float(hi.x));
      hi.y = f2tf32(kv.y); lo.y = f2tf32(kv.y - __uint_as_float(hi.y));
      hi.z = f2tf32(kv.z); lo.z = f2tf32(kv.z - __uint_as_float(hi.z));
      hi.w = f2tf32(kv.w); lo.w = f2tf32(kv.w - __uint_as_float(hi.w));
      *(uint4*)&KH[r * KS_ST + d4] = hi;
      *(uint4*)&KL[r * KS_ST + d4] = lo;
      float4 vv = *(const float4*)(Kg + GROUPS_ * KVC_ +
                                   (size_t)r * (2 * GROUPS_ * KVC_) + d4);
      uint4 uv = make_uint4(f2tf32(vv.x), f2tf32(vv.y), f2tf32(vv.z),
                            f2tf32(vv.w));
      *(uint4*)&Vs[r * VS_ST2 + d4] = uv;
    }
    __syncthreads();

    // warp strip fully masked for this kv tile? (still hit the syncs above)
    bool active = (jt * 64) <= (qt * 128 + rbase + 15);
    if (active) {
      // ---- S = Q @ K^T (hi + lo) ----
      float sacc[8][4];
#pragma unroll
      for (int nt = 0; nt < 8; nt++)
#pragma unroll
        for (int i = 0; i < 4; i++) sacc[nt][i] = 0.f;

#pragma unroll 2
      for (int kk = 0; kk < 128; kk += 8) {
        uint32_t a[4];
        int ra = (rbase + gid) * QS_ST + kk + tig;
        a[0] = Qs[ra];
        a[1] = Qs[ra + 8 * QS_ST];
        a[2] = Qs[ra + 4];
        a[3] = Qs[ra + 8 * QS_ST + 4];
#pragma unroll
        for (int nt = 0; nt < 8; nt++) {
          int rk = (nt * 8 + gid) * KS_ST + kk + tig;
          uint32_t bh[2] = {KH[rk], KH[rk + 4]};
          uint32_t bl[2] = {KL[rk], KL[rk + 4]};
          mma_tf32(sacc[nt], a, bh);
          mma_tf32(sacc[nt], a, bl);
        }
      }

      // ---- causal mask (only when tile touches the diagonal) ----
      int rowg0 = qt * 128 + rbase + gid;
      int rowg1 = rowg0 + 8;
      if (jt * 64 + 63 > rowg0) {
#pragma unroll
        for (int nt = 0; nt < 8; nt++) {
          int colg = jt * 64 + nt * 8 + 2 * tig;
          if (colg > rowg0) sacc[nt][0] = -1e30f;
          if (colg + 1 > rowg0) sacc[nt][1] = -1e30f;
          if (colg > rowg1) sacc[nt][2] = -1e30f;
          if (colg + 1 > rowg1) sacc[nt][3] = -1e30f;
        }
      }

      // ---- online softmax (log2 domain), rows gid / gid+8 ----
      float rm0 = -1e30f, rm1 = -1e30f;
#pragma unroll
      for (int nt = 0; nt < 8; nt++) {
        rm0 = fmaxf(rm0, fmaxf(sacc[nt][0], sacc[nt][1]));
        rm1 = fmaxf(rm1, fmaxf(sacc[nt][2], sacc[nt][3]));
      }
      rm0 = fmaxf(rm0, __shfl_xor_sync(0xffffffffu, rm0, 1));
      rm0 = fmaxf(rm0, __shfl_xor_sync(0xffffffffu, rm0, 2));
      rm1 = fmaxf(rm1, __shfl_xor_sync(0xffffffffu, rm1, 1));
      rm1 = fmaxf(rm1, __shfl_xor_sync(0xffffffffu, rm1, 2));

      float mn0 = fmaxf(m0, rm0), mn1 = fmaxf(m1, rm1);
      float al0 = ex2f(m0 - mn0), al1 = ex2f(m1 - mn1);
      m0 = mn0; m1 = mn1;

      float rs0 = 0.f, rs1 = 0.f;
#pragma unroll
      for (int nt = 0; nt < 8; nt++) {
        float p0 = ex2f(sacc[nt][0] - mn0);
        float p1 = ex2f(sacc[nt][1] - mn0);
        float p2 = ex2f(sacc[nt][2] - mn1);
        float p3 = ex2f(sacc[nt][3] - mn1);
        rs0 += p0 + p1;
        rs1 += p2 + p3;
        uint2 w01 = make_uint2(f2tf32(p0), f2tf32(p1));
        uint2 w23 = make_uint2(f2tf32(p2), f2tf32(p3));
        int c = nt * 8 + 2 * tig;
        *(uint2*)&Ps[(rbase + gid) * PS_ST2 + c] = w01;
        *(uint2*)&Ps[(rbase + gid + 8) * PS_ST2 + c] = w23;
      }
      rs0 += __shfl_xor_sync(0xffffffffu, rs0, 1);
      rs0 += __shfl_xor_sync(0xffffffffu, rs0, 2);
      rs1 += __shfl_xor_sync(0xffffffffu, rs1, 1);
      rs1 += __shfl_xor_sync(0xffffffffu, rs1, 2);
      l0 = l0 * al0 + rs0;
      l1 = l1 * al1 + rs1;

#pragma unroll
      for (int nt = 0; nt < 16; nt++) {
        O[nt][0] *= al0;
        O[nt][1] *= al0;
        O[nt][2] *= al1;
        O[nt][3] *= al1;
      }
      __syncwarp();  // Ps stores visible to this warp's fragment loads

      // ---- O += P @ V ----
#pragma unroll 2
      for (int kk = 0; kk < 64; kk += 8) {
        uint32_t a[4];
        int rp = (rbase + gid) * PS_ST2 + kk + tig;
        a[0] = Ps[rp];
        a[1] = Ps[rp + 8 * PS_ST2];
        a[2] = Ps[rp + 4];
        a[3] = Ps[rp + 8 * PS_ST2 + 4];
#pragma unroll
        for (int nt = 0; nt < 16; nt++) {
          int rv = (kk + tig) * VS_ST2 + nt * 8 + gid;
          uint32_t bv[2] = {Vs[rv], Vs[rv + 4 * VS_ST2]};
          mma_tf32(O[nt], a, bv);
        }
      }
    }
  }

  // ---- epilogue: normalize + write ctx ----
  float inv0 = 1.f / l0, inv1 = 1.f / l1;
  size_t row0 = (size_t)b * S_ + qt * 128 + rbase + gid;
  float* c0 = g_ctx + (row0 * HEADS_ + h) * KVC_;
  float* c1 = g_ctx + ((row0 + 8) * HEADS_ + h) * KVC_;
#pragma unroll
  for (int nt = 0; nt < 16; nt++) {
    int c = nt * 8 + 2 * tig;
    *(float2*)&c0[c] = make_float2(O[nt][0] * inv0, O[nt][1] * inv0);
    *(float2*)&c1[c] = make_float2(O[nt][2] * inv1, O[nt][3] * inv1);
  }
}

// ---------------------------------------------------------------------------
extern "C" void kernel_launch(void* const* d_in, const int* in_sizes, int n_in,
                              void* d_out, int out_size) {
  (void)in_sizes; (void)n_in; (void)out_size;
  const float* x = (const float*)d_in[0];
  const float* w_q = (const float*)d_in[1];
  const float* w_kv = (const float*)d_in[2];
  const float* w_dense = (const float*)d_in[3];
  float* out = (float*)d_out;

  float *qb, *kvb, *ctxb;
  cudaGetSymbolAddress((void**)&qb, g_q);
  cudaGetSymbolAddress((void**)&kvb, g_kv);
  cudaGetSymbolAddress((void**)&ctxb, g_ctx);

  cudaFuncSetAttribute(tf32gemm2, cudaFuncAttributeMaxDynamicSharedMemorySize,
                       GEMM_SMEM);
  cudaFuncSetAttribute(attn_tc, cudaFuncAttributeMaxDynamicSharedMemorySize,
                       ATTN2_SMEM);

  // 1) fused QKV projections: block cols 0..15 -> q, 16..23 -> kv
  tf32gemm2<<<dim3(16 + 8, 32), 256, GEMM_SMEM>>>(
      HID_, x, w_q, HEADS_ * KVC_, qb, w_kv, 2 * GROUPS_ * KVC_, kvb);
  // 2) RoPE
  rope_tables_k<<<(S_ * 64 + 255) / 256, 256>>>();
  rope_apply_k<<<(B_ * S_ * (HEADS_ + GROUPS_) * 64 + 255) / 256, 256>>>();
  // 3) causal GQA flash attention (tensor cores)
  attn_tc<<<dim3(S_ / 128, B_ * HEADS_), 256, ATTN2_SMEM>>>();
  // 4) dense projection -> out
  tf32gemm2<<<dim3(16, 32), 256, GEMM_SMEM>>>(
      HEADS_ * KVC_, ctxb, w_dense, HID_, out, w_dense, HID_, out);
}